// round 15
// baseline (speedup 1.0000x reference)
#include <cuda_runtime.h>
#include <cuda_fp16.h>
#include <cstdint>

#define BB 32
#define NN 1024
#define DD 512
#define LN_EPS 1e-5f

// ---------------- scratch (no allocations allowed) ----------------
__device__ float  g_denom[BB * NN];
__device__ float  g_x[BB * NN * DD];                 // fp32 layer activations
__device__ __half g_adj_h[(size_t)BB * NN * NN];     // adj fp16
__device__ __half g_xT_h[(size_t)BB * DD * NN];      // X^T fp16 (B of gemm1)
__device__ __half g_y_h[(size_t)BB * NN * DD];       // gemm1 output fp16 (A of gemm2)
__device__ __half g_W0_h[DD * DD];
__device__ __half g_W1_h[DD * DD];

// ---------------- PTX helpers (base sm_103-safe) ----------------
__device__ __forceinline__ uint32_t smem_u32(const void* p) {
    uint32_t a;
    asm("{ .reg .u64 t; cvta.to.shared.u64 t, %1; cvt.u32.u64 %0, t; }" : "=r"(a) : "l"(p));
    return a;
}
__device__ __forceinline__ void cp_async16(uint32_t dst, const void* src) {
    asm volatile("cp.async.cg.shared.global [%0], [%1], 16;" :: "r"(dst), "l"(src));
}
__device__ __forceinline__ void cp_commit() { asm volatile("cp.async.commit_group;" ::: "memory"); }
template <int N>
__device__ __forceinline__ void cp_wait() { asm volatile("cp.async.wait_group %0;" :: "n"(N) : "memory"); }

__device__ __forceinline__ void ldsm4(uint32_t* r, uint32_t addr) {
    asm volatile("ldmatrix.sync.aligned.m8n8.x4.shared.b16 {%0,%1,%2,%3}, [%4];"
                 : "=r"(r[0]), "=r"(r[1]), "=r"(r[2]), "=r"(r[3]) : "r"(addr));
}
__device__ __forceinline__ void mma16816(float* c, const uint32_t* a, const uint32_t* b) {
    asm volatile("mma.sync.aligned.m16n8k16.row.col.f32.f16.f16.f32 "
                 "{%0,%1,%2,%3}, {%4,%5,%6,%7}, {%8,%9}, {%0,%1,%2,%3};"
                 : "+f"(c[0]), "+f"(c[1]), "+f"(c[2]), "+f"(c[3])
                 : "r"(a[0]), "r"(a[1]), "r"(a[2]), "r"(a[3]), "r"(b[0]), "r"(b[1]));
}

// ---------------- reductions ----------------
__device__ __forceinline__ float block_reduce_sum(float v, float* sh) {
    __syncthreads();
    int tid = threadIdx.x;
    #pragma unroll
    for (int o = 16; o > 0; o >>= 1) v += __shfl_down_sync(0xffffffff, v, o);
    if ((tid & 31) == 0) sh[tid >> 5] = v;
    __syncthreads();
    if (tid < 32) {
        v = (tid < (int)(blockDim.x >> 5)) ? sh[tid] : 0.0f;
        #pragma unroll
        for (int o = 16; o > 0; o >>= 1) v += __shfl_down_sync(0xffffffff, v, o);
        if (tid == 0) sh[0] = v;
    }
    __syncthreads();
    return sh[0];
}

// ---------------- adj pass: rowsum+1 -> denom, fp16 convert ----------------
__global__ void __launch_bounds__(256)
adj_pass_kernel(const float* __restrict__ adj, float* __restrict__ denom,
                __half* __restrict__ Ah) {
    __shared__ float rowacc[128];
    const int b = blockIdx.y;
    const int r0 = blockIdx.x * 128;
    const int tid = threadIdx.x;
    const int lane = tid & 31;
    const int col0 = tid * 4;

    for (int i = tid; i < 128; i += 256) rowacc[i] = 0.0f;
    __syncthreads();

    const float* src = adj + (size_t)b * NN * NN + (size_t)r0 * NN;
    __half* dh = Ah + (size_t)b * NN * NN + (size_t)r0 * NN;

    for (int r = 0; r < 128; r++) {
        float4 v = *reinterpret_cast<const float4*>(&src[(size_t)r * NN + col0]);
        __half h0 = __float2half_rn(v.x), h1 = __float2half_rn(v.y);
        __half h2 = __float2half_rn(v.z), h3 = __float2half_rn(v.w);
        *reinterpret_cast<__half2*>(&dh[(size_t)r * NN + col0])     = __halves2half2(h0, h1);
        *reinterpret_cast<__half2*>(&dh[(size_t)r * NN + col0 + 2]) = __halves2half2(h2, h3);
        float s = (v.x + v.y) + (v.z + v.w);
        #pragma unroll
        for (int o = 16; o > 0; o >>= 1) s += __shfl_down_sync(0xffffffff, s, o);
        if (lane == 0) atomicAdd(&rowacc[r], s);
    }
    __syncthreads();
    if (tid < 128) denom[(size_t)b * NN + r0 + tid] = rowacc[tid] + 1.0f;
}

// both weights fp32 -> fp16
__global__ void splitW2_kernel(const float* __restrict__ w0, const float* __restrict__ w1,
                               __half* __restrict__ h0, __half* __restrict__ h1) {
    int i = blockIdx.x * blockDim.x + threadIdx.x;
    if (i >= DD * DD / 4) return;
    const float* src = blockIdx.y ? w1 : w0;
    __half* dst = blockIdx.y ? h1 : h0;
    float4 v = reinterpret_cast<const float4*>(src)[i];
    reinterpret_cast<__half2*>(dst)[i * 2 + 0] =
        __halves2half2(__float2half_rn(v.x), __float2half_rn(v.y));
    reinterpret_cast<__half2*>(dst)[i * 2 + 1] =
        __halves2half2(__float2half_rn(v.z), __float2half_rn(v.w));
}

// x[b][m][d] fp32 -> x^T fp16 [b][d][m]
__global__ void transpose_h(const float* __restrict__ x, __half* __restrict__ th) {
    __shared__ float tile[32][33];
    int b = blockIdx.z;
    int m0 = blockIdx.y * 32, d0 = blockIdx.x * 32;
    const float* src = x + (size_t)b * NN * DD;
    int tx = threadIdx.x, ty = threadIdx.y;
    #pragma unroll
    for (int j = 0; j < 32; j += 8)
        tile[ty + j][tx] = src[(size_t)(m0 + ty + j) * DD + d0 + tx];
    __syncthreads();
    __half* dh = th + (size_t)b * DD * NN;
    #pragma unroll
    for (int j = 0; j < 32; j += 8)
        dh[(size_t)(d0 + ty + j) * NN + m0 + tx] = __float2half_rn(tile[tx][ty + j]);
}

// ================= GEMM1: Y = adj@x + x -> yh fp16 ==================
// CTA tile 128x128, warp tile 32x64 (4 m-warps x 2 n-warps), KT=64, 2 CTAs/SM.
#define KT 64
#define A1_TB 16384                       // 128 rows x 128 B
#define B1_TB 16384                       // 128 rows x 128 B
#define STAGE1 (A1_TB + B1_TB)            // 32 KB
#define G1_SMEM (2 * STAGE1)              // 64 KB

__global__ void __launch_bounds__(256, 2)
gemm1_hmma(const __half* __restrict__ A, const __half* __restrict__ Bh,
           const float* __restrict__ Xadd, __half* __restrict__ OutH) {
    extern __shared__ char smem[];
    const uint32_t sb = smem_u32(smem);
    const int tid = threadIdx.x;
    const int wid = tid >> 5;
    const int lane = tid & 31;

    const int b = blockIdx.z;
    const long aRow0 = (long)b * NN + blockIdx.y * 128;
    const long bRow0 = (long)b * DD + blockIdx.x * 128;
    const long outRow0 = aRow0;
    const int colBlk = blockIdx.x * 128;

    const __half* srcA   = A  + aRow0 * NN;
    const __half* srcB_h = Bh + bRow0 * NN;

    const int m0 = (wid & 3) * 32;
    const int n0 = (wid >> 2) * 64;

    const int ltile = lane >> 3;
    const int rowInTile = (lane & 7) + ((ltile & 1) << 3);
    const int kk = ltile >> 1;
    const int lx = lane & 7;

    float acc[2][8][4];
    #pragma unroll
    for (int a = 0; a < 2; a++)
        #pragma unroll
        for (int b2 = 0; b2 < 8; b2++)
            #pragma unroll
            for (int c = 0; c < 4; c++) acc[a][b2][c] = 0.0f;

    const int nk = NN / KT;   // 16

    auto issue = [&](int i) {
        const uint32_t stg = sb + (uint32_t)(i & 1) * STAGE1;
        const int k0 = i * KT;
        #pragma unroll
        for (int jj = 0; jj < 4; jj++) {           // A: 1024 chunks
            int cid = tid + jj * 256;
            int row = cid >> 3, c = cid & 7;
            cp_async16(stg + row * 128 + ((c ^ (row & 7)) << 4),
                       srcA + (size_t)row * NN + k0 + c * 8);
        }
        #pragma unroll
        for (int jj = 0; jj < 4; jj++) {           // B: 1024 chunks
            int cid = tid + jj * 256;
            int row = cid >> 3, c = cid & 7;
            cp_async16(stg + A1_TB + row * 128 + ((c ^ (row & 7)) << 4),
                       srcB_h + (size_t)row * NN + k0 + c * 8);
        }
        cp_commit();
    };

    issue(0);

    for (int i = 0; i < nk; i++) {
        if (i + 1 < nk) issue(i + 1);
        if (i + 1 < nk) cp_wait<1>(); else cp_wait<0>();
        __syncthreads();

        const uint32_t stg = sb + (uint32_t)(i & 1) * STAGE1;
        const uint32_t sA = stg, sBh = stg + A1_TB;

        #pragma unroll
        for (int ks = 0; ks < 4; ks++) {
            const uint32_t swz = (uint32_t)(((ks * 2 + kk) ^ lx) << 4);
            uint32_t af[2][4], bh[8][2];
            #pragma unroll
            for (int mf = 0; mf < 2; mf++) {
                uint32_t off = (uint32_t)((m0 + mf * 16 + rowInTile) * 128) + swz;
                ldsm4(af[mf], sA + off);
            }
            #pragma unroll
            for (int nh = 0; nh < 4; nh++) {
                uint32_t off = (uint32_t)((n0 + nh * 16 + rowInTile) * 128) + swz;
                uint32_t r[4];
                ldsm4(r, sBh + off);
                bh[nh * 2][0] = r[0]; bh[nh * 2][1] = r[2];
                bh[nh * 2 + 1][0] = r[1]; bh[nh * 2 + 1][1] = r[3];
            }
            #pragma unroll
            for (int mf = 0; mf < 2; mf++)
                #pragma unroll
                for (int nf = 0; nf < 8; nf++)
                    mma16816(acc[mf][nf], af[mf], bh[nf]);
        }
        __syncthreads();
    }

    // ---- epilogue: +X, write yh fp16 ----
    const int rr = lane >> 2;
    const int cc = (lane & 3) * 2;
    #pragma unroll
    for (int mf = 0; mf < 2; mf++) {
        #pragma unroll
        for (int hf = 0; hf < 2; hf++) {
            long grow = outRow0 + m0 + mf * 16 + rr + hf * 8;
            #pragma unroll
            for (int nf = 0; nf < 8; nf++) {
                int gcol = colBlk + n0 + nf * 8 + cc;
                size_t gi = (size_t)grow * DD + gcol;
                float v0 = acc[mf][nf][hf * 2 + 0];
                float v1 = acc[mf][nf][hf * 2 + 1];
                float2 xv = *reinterpret_cast<const float2*>(&Xadd[gi]);
                v0 += xv.x; v1 += xv.y;
                *reinterpret_cast<__half2*>(&OutH[gi]) =
                    __halves2half2(__float2half_rn(v0), __float2half_rn(v1));
            }
        }
    }
}

// ===== GEMM2: X' = relu((yh@Wh^T + 2b)/denom) -> fp32 (+ optional x^T fp16) ====
#define A2_TB 16384                        // 128 rows x 128 B
#define B2_TB 16384                        // 128 rows x 128 B
#define STAGE2 (A2_TB + B2_TB)             // 32 KB
#define G2_SMEM (2 * STAGE2)               // 64 KB
#define TSTRIDE 136                        // transposed-stage row stride (halves)

__global__ void __launch_bounds__(256, 2)
gemm2_hmma(const __half* __restrict__ A, const __half* __restrict__ Bh,
           const float* __restrict__ bias, const float* __restrict__ denom,
           float* __restrict__ OutF, __half* __restrict__ OutT) {
    extern __shared__ char smem[];
    const uint32_t sb = smem_u32(smem);
    const int tid = threadIdx.x;
    const int wid = tid >> 5;
    const int lane = tid & 31;

    const long aRow0 = (long)blockIdx.y * 128;
    const long bRow0 = (long)blockIdx.x * 128;
    const int colBlk = blockIdx.x * 128;

    const __half* srcA   = A  + aRow0 * DD;
    const __half* srcB_h = Bh + bRow0 * DD;

    const int m0 = (wid & 3) * 32;
    const int n0 = (wid >> 2) * 64;

    const int ltile = lane >> 3;
    const int rowInTile = (lane & 7) + ((ltile & 1) << 3);
    const int kk = ltile >> 1;
    const int lx = lane & 7;

    float acc[2][8][4];
    #pragma unroll
    for (int a = 0; a < 2; a++)
        #pragma unroll
        for (int b2 = 0; b2 < 8; b2++)
            #pragma unroll
            for (int c = 0; c < 4; c++) acc[a][b2][c] = 0.0f;

    const int nk = DD / KT;   // 8

    auto issue = [&](int i) {
        const uint32_t stg = sb + (uint32_t)(i & 1) * STAGE2;
        const int k0 = i * KT;
        #pragma unroll
        for (int jj = 0; jj < 4; jj++) {           // A: 1024 chunks
            int cid = tid + jj * 256;
            int row = cid >> 3, c = cid & 7;
            cp_async16(stg + row * 128 + ((c ^ (row & 7)) << 4),
                       srcA + (size_t)row * DD + k0 + c * 8);
        }
        #pragma unroll
        for (int jj = 0; jj < 4; jj++) {           // B: 1024 chunks
            int cid = tid + jj * 256;
            int row = cid >> 3, c = cid & 7;
            cp_async16(stg + A2_TB + row * 128 + ((c ^ (row & 7)) << 4),
                       srcB_h + (size_t)row * DD + k0 + c * 8);
        }
        cp_commit();
    };

    issue(0);

    for (int i = 0; i < nk; i++) {
        if (i + 1 < nk) issue(i + 1);
        if (i + 1 < nk) cp_wait<1>(); else cp_wait<0>();
        __syncthreads();

        const uint32_t stg = sb + (uint32_t)(i & 1) * STAGE2;
        const uint32_t sA = stg, sBh = stg + A2_TB;

        #pragma unroll
        for (int ks = 0; ks < 4; ks++) {
            const uint32_t swz = (uint32_t)(((ks * 2 + kk) ^ lx) << 4);
            uint32_t af[2][4], bh[8][2];
            #pragma unroll
            for (int mf = 0; mf < 2; mf++) {
                uint32_t off = (uint32_t)((m0 + mf * 16 + rowInTile) * 128) + swz;
                ldsm4(af[mf], sA + off);
            }
            #pragma unroll
            for (int nh = 0; nh < 4; nh++) {
                uint32_t off = (uint32_t)((n0 + nh * 16 + rowInTile) * 128) + swz;
                uint32_t r[4];
                ldsm4(r, sBh + off);
                bh[nh * 2][0] = r[0]; bh[nh * 2][1] = r[2];
                bh[nh * 2 + 1][0] = r[1]; bh[nh * 2 + 1][1] = r[3];
            }
            #pragma unroll
            for (int mf = 0; mf < 2; mf++)
                #pragma unroll
                for (int nf = 0; nf < 8; nf++)
                    mma16816(acc[mf][nf], af[mf], bh[nf]);
        }
        __syncthreads();
    }

    // ---- epilogue: relu((v + 2b)/denom) -> OutF; optionally stage x^T fp16 ----
    __half* sT = reinterpret_cast<__half*>(smem);   // 128 x 128 transposed stage
    const int rr = lane >> 2;
    const int cc = (lane & 3) * 2;
    #pragma unroll
    for (int mf = 0; mf < 2; mf++) {
        #pragma unroll
        for (int hf = 0; hf < 2; hf++) {
            long grow = aRow0 + m0 + mf * 16 + rr + hf * 8;
            float invd = 1.0f / denom[grow];
            int ml = m0 + mf * 16 + rr + hf * 8;   // local row 0..127
            #pragma unroll
            for (int nf = 0; nf < 8; nf++) {
                int dl = n0 + nf * 8 + cc;          // local col 0..127
                int gcol = colBlk + dl;
                size_t gi = (size_t)grow * DD + gcol;
                float2 bv = *reinterpret_cast<const float2*>(&bias[gcol]);
                float2 o;
                o.x = fmaxf((acc[mf][nf][hf * 2 + 0] + 2.0f * bv.x) * invd, 0.0f);
                o.y = fmaxf((acc[mf][nf][hf * 2 + 1] + 2.0f * bv.y) * invd, 0.0f);
                *reinterpret_cast<float2*>(&OutF[gi]) = o;
                if (OutT) {
                    sT[(dl + 0) * TSTRIDE + ml] = __float2half_rn(o.x);
                    sT[(dl + 1) * TSTRIDE + ml] = __float2half_rn(o.y);
                }
            }
        }
    }
    if (OutT) {
        __syncthreads();
        const int bb = (int)(aRow0 >> 10);          // aRow0 / NN
        const int m0g = (int)(aRow0 & (NN - 1));    // aRow0 % NN
        __half* dst = OutT + (size_t)bb * DD * NN + (size_t)colBlk * NN + m0g;
        for (int it = tid; it < 128 * 64; it += 256) {
            int d = it >> 6;
            int mw = (it & 63) * 2;
            uint32_t v = *reinterpret_cast<uint32_t*>(&sT[d * TSTRIDE + mw]);
            *reinterpret_cast<uint32_t*>(&dst[(size_t)d * NN + mw]) = v;
        }
    }
}

// ---------------- LayerNorm ----------------
__global__ void ln_kernel(const float* __restrict__ X, const float* __restrict__ g,
                          const float* __restrict__ b, float* __restrict__ out) {
    __shared__ float sh[32];
    const int row = blockIdx.x;
    const float* p = X + (size_t)row * DD;
    const int tid = threadIdx.x;
    float v0 = p[tid];
    float v1 = p[tid + 256];
    float mu = block_reduce_sum(v0 + v1, sh) * (1.0f / DD);
    float d0 = v0 - mu, d1 = v1 - mu;
    float var = block_reduce_sum(d0 * d0 + d1 * d1, sh) * (1.0f / DD);
    float r = rsqrtf(var + LN_EPS);
    out[(size_t)row * DD + tid] = d0 * r * g[tid] + b[tid];
    out[(size_t)row * DD + tid + 256] = d1 * r * g[tid + 256] + b[tid + 256];
}

// masks: (rowsum + colsum) == 0; colsum from fp16 adj (zero/nonzero preserved)
__global__ void mask_kernel(const float* __restrict__ denom, const __half* __restrict__ Ah,
                            float* __restrict__ out, int count) {
    int i = blockIdx.x * blockDim.x + threadIdx.x;
    if (i >= count) return;
    if (i < BB * NN) {
        int b = i >> 10, m = i & (NN - 1);
        const __half* p = Ah + (size_t)b * NN * NN + m;
        float cs = 0.0f;
        #pragma unroll 4
        for (int n = 0; n < NN; n++) cs += __half2float(p[(size_t)n * NN]);
        float rs = denom[i] - 1.0f;
        out[i] = ((rs + cs) == 0.0f) ? 1.0f : 0.0f;
    } else {
        out[i] = 0.0f;
    }
}

// ---------------- launch ----------------
extern "C" void kernel_launch(void* const* d_in, const int* in_sizes, int n_in,
                              void* d_out, int out_size) {
    const float* adj = (const float*)d_in[0];
    const float* emb = (const float*)d_in[1];
    const float* W0w = (const float*)d_in[3];
    const float* W0b = (const float*)d_in[4];
    const float* W1w = (const float*)d_in[5];
    const float* W1b = (const float*)d_in[6];
    const float* lng = (const float*)d_in[7];
    const float* lnb = (const float*)d_in[8];
    float* out = (float*)d_out;

    float *denom, *x;
    __half *adjh, *xth, *yh, *w0h, *w1h;
    cudaGetSymbolAddress((void**)&denom, g_denom);
    cudaGetSymbolAddress((void**)&x, g_x);
    cudaGetSymbolAddress((void**)&adjh, g_adj_h);
    cudaGetSymbolAddress((void**)&xth, g_xT_h);
    cudaGetSymbolAddress((void**)&yh, g_y_h);
    cudaGetSymbolAddress((void**)&w0h, g_W0_h);
    cudaGetSymbolAddress((void**)&w1h, g_W1_h);

    cudaFuncSetAttribute(gemm1_hmma, cudaFuncAttributeMaxDynamicSharedMemorySize, G1_SMEM);
    cudaFuncSetAttribute(gemm2_hmma, cudaFuncAttributeMaxDynamicSharedMemorySize, G2_SMEM);

    dim3 tg(DD / 32, NN / 32, BB);
    dim3 tb(32, 8);
    dim3 ga(8, BB);
    dim3 g1(DD / 128, NN / 128, BB);        // (4, 8, 32)
    dim3 g2(DD / 128, (BB * NN) / 128, 1);  // (4, 256)
    int w4 = (DD * DD) / 4;

    adj_pass_kernel<<<ga, 256>>>(adj, denom, adjh);                            // 1
    transpose_h<<<tg, tb>>>(emb, xth);                                         // 2
    splitW2_kernel<<<dim3((w4 + 255) / 256, 2), 256>>>(W0w, W1w, w0h, w1h);    // 3
    gemm1_hmma<<<g1, 256, G1_SMEM>>>(adjh, xth, emb, yh);                      // 4
    gemm2_hmma<<<g2, 256, G2_SMEM>>>(yh, w0h, W0b, denom, x, xth);             // 5 (writes x^T)
    gemm1_hmma<<<g1, 256, G1_SMEM>>>(adjh, xth, x, yh);                        // 6
    gemm2_hmma<<<g2, 256, G2_SMEM>>>(yh, w1h, W1b, denom, x, nullptr);         // 7
    ln_kernel<<<BB * NN, 256>>>(x, lng, lnb, out);                             // 8

    int extra = out_size - BB * NN * DD;
    if (extra > 0) {
        mask_kernel<<<(extra + 255) / 256, 256>>>(denom, adjh,
                                                  out + (size_t)BB * NN * DD, extra);
    }
}

// round 16
// speedup vs baseline: 1.2517x; 1.2517x over previous
#include <cuda_runtime.h>
#include <cuda_fp16.h>
#include <cstdint>

#define BB 32
#define NN 1024
#define DD 512
#define LN_EPS 1e-5f

// ---------------- scratch (no allocations allowed) ----------------
__device__ float  g_denom[BB * NN];
__device__ float  g_colsum[BB * NN];
__device__ float  g_x[BB * NN * DD];                 // fp32 layer activations
__device__ __half g_adj_h[(size_t)BB * NN * NN];     // adj fp16
__device__ __half g_xT_h[(size_t)BB * DD * NN];      // X^T fp16 (B of gemm1)
__device__ __half g_y_h[(size_t)BB * NN * DD];       // gemm1 output fp16 (A of gemm2)
__device__ __half g_W0_h[DD * DD];
__device__ __half g_W1_h[DD * DD];

// ---------------- PTX helpers (base sm_103-safe) ----------------
__device__ __forceinline__ uint32_t smem_u32(const void* p) {
    uint32_t a;
    asm("{ .reg .u64 t; cvta.to.shared.u64 t, %1; cvt.u32.u64 %0, t; }" : "=r"(a) : "l"(p));
    return a;
}
__device__ __forceinline__ void cp_async16(uint32_t dst, const void* src) {
    asm volatile("cp.async.cg.shared.global [%0], [%1], 16;" :: "r"(dst), "l"(src));
}
__device__ __forceinline__ void cp_commit() { asm volatile("cp.async.commit_group;" ::: "memory"); }
template <int N>
__device__ __forceinline__ void cp_wait() { asm volatile("cp.async.wait_group %0;" :: "n"(N) : "memory"); }

__device__ __forceinline__ void ldsm4(uint32_t* r, uint32_t addr) {
    asm volatile("ldmatrix.sync.aligned.m8n8.x4.shared.b16 {%0,%1,%2,%3}, [%4];"
                 : "=r"(r[0]), "=r"(r[1]), "=r"(r[2]), "=r"(r[3]) : "r"(addr));
}
__device__ __forceinline__ void mma16816(float* c, const uint32_t* a, const uint32_t* b) {
    asm volatile("mma.sync.aligned.m16n8k16.row.col.f32.f16.f16.f32 "
                 "{%0,%1,%2,%3}, {%4,%5,%6,%7}, {%8,%9}, {%0,%1,%2,%3};"
                 : "+f"(c[0]), "+f"(c[1]), "+f"(c[2]), "+f"(c[3])
                 : "r"(a[0]), "r"(a[1]), "r"(a[2]), "r"(a[3]), "r"(b[0]), "r"(b[1]));
}

// ---------------- reductions ----------------
__device__ __forceinline__ float block_reduce_sum(float v, float* sh) {
    __syncthreads();
    int tid = threadIdx.x;
    #pragma unroll
    for (int o = 16; o > 0; o >>= 1) v += __shfl_down_sync(0xffffffff, v, o);
    if ((tid & 31) == 0) sh[tid >> 5] = v;
    __syncthreads();
    if (tid < 32) {
        v = (tid < (int)(blockDim.x >> 5)) ? sh[tid] : 0.0f;
        #pragma unroll
        for (int o = 16; o > 0; o >>= 1) v += __shfl_down_sync(0xffffffff, v, o);
        if (tid == 0) sh[0] = v;
    }
    __syncthreads();
    return sh[0];
}

// ---------------- adj pass: rowsum+1 -> denom, colsum (atomic), fp16 ----------
__global__ void __launch_bounds__(256)
adj_pass_kernel(const float* __restrict__ adj, float* __restrict__ denom,
                float* __restrict__ colsum, __half* __restrict__ Ah) {
    __shared__ float rowacc[128];
    const int b = blockIdx.y;
    const int r0 = blockIdx.x * 128;
    const int tid = threadIdx.x;
    const int lane = tid & 31;
    const int col0 = tid * 4;

    for (int i = tid; i < 128; i += 256) rowacc[i] = 0.0f;
    __syncthreads();

    const float* src = adj + (size_t)b * NN * NN + (size_t)r0 * NN;
    __half* dh = Ah + (size_t)b * NN * NN + (size_t)r0 * NN;

    float cs0 = 0.f, cs1 = 0.f, cs2 = 0.f, cs3 = 0.f;

    for (int r = 0; r < 128; r++) {
        float4 v = *reinterpret_cast<const float4*>(&src[(size_t)r * NN + col0]);
        __half h0 = __float2half_rn(v.x), h1 = __float2half_rn(v.y);
        __half h2 = __float2half_rn(v.z), h3 = __float2half_rn(v.w);
        *reinterpret_cast<__half2*>(&dh[(size_t)r * NN + col0])     = __halves2half2(h0, h1);
        *reinterpret_cast<__half2*>(&dh[(size_t)r * NN + col0 + 2]) = __halves2half2(h2, h3);
        cs0 += v.x; cs1 += v.y; cs2 += v.z; cs3 += v.w;
        float s = (v.x + v.y) + (v.z + v.w);
        #pragma unroll
        for (int o = 16; o > 0; o >>= 1) s += __shfl_down_sync(0xffffffff, s, o);
        if (lane == 0) atomicAdd(&rowacc[r], s);
    }
    __syncthreads();
    if (tid < 128) denom[(size_t)b * NN + r0 + tid] = rowacc[tid] + 1.0f;
    float* cdst = colsum + (size_t)b * NN + col0;
    atomicAdd(cdst + 0, cs0);
    atomicAdd(cdst + 1, cs1);
    atomicAdd(cdst + 2, cs2);
    atomicAdd(cdst + 3, cs3);
}

__global__ void zero_kernel(float* __restrict__ p, int n) {
    int i = blockIdx.x * blockDim.x + threadIdx.x;
    if (i < n) p[i] = 0.0f;
}

// both weights fp32 -> fp16 (one launch)
__global__ void splitW2_kernel(const float* __restrict__ w0, const float* __restrict__ w1,
                               __half* __restrict__ h0, __half* __restrict__ h1) {
    int i = blockIdx.x * blockDim.x + threadIdx.x;
    if (i >= DD * DD / 4) return;
    const float* src = blockIdx.y ? w1 : w0;
    __half* dst = blockIdx.y ? h1 : h0;
    float4 v = reinterpret_cast<const float4*>(src)[i];
    reinterpret_cast<__half2*>(dst)[i * 2 + 0] =
        __halves2half2(__float2half_rn(v.x), __float2half_rn(v.y));
    reinterpret_cast<__half2*>(dst)[i * 2 + 1] =
        __halves2half2(__float2half_rn(v.z), __float2half_rn(v.w));
}

// x[b][m][d] fp32 -> x^T fp16 [b][d][m]
__global__ void transpose_h(const float* __restrict__ x, __half* __restrict__ th) {
    __shared__ float tile[32][33];
    int b = blockIdx.z;
    int m0 = blockIdx.y * 32, d0 = blockIdx.x * 32;
    const float* src = x + (size_t)b * NN * DD;
    int tx = threadIdx.x, ty = threadIdx.y;
    #pragma unroll
    for (int j = 0; j < 32; j += 8)
        tile[ty + j][tx] = src[(size_t)(m0 + ty + j) * DD + d0 + tx];
    __syncthreads();
    __half* dh = th + (size_t)b * DD * NN;
    #pragma unroll
    for (int j = 0; j < 32; j += 8)
        dh[(size_t)(d0 + ty + j) * NN + m0 + tx] = __float2half_rn(tile[tx][ty + j]);
}

// ================= GEMM1: Y = adj@x + x -> yh fp16 (128x128 CTA tile) =========
#define KT 64
#define A1_TB 16384                       // 128 rows x 128 B
#define B1_TB 16384                       // 128 rows x 128 B
#define STAGE1 (A1_TB + B1_TB)            // 32 KB
#define G1_SMEM (2 * STAGE1)              // 64 KB

__global__ void __launch_bounds__(256, 2)
gemm1_hmma(const __half* __restrict__ A, const __half* __restrict__ Bh,
           const float* __restrict__ Xadd, __half* __restrict__ OutH) {
    extern __shared__ char smem[];
    const uint32_t sb = smem_u32(smem);
    const int tid = threadIdx.x;
    const int wid = tid >> 5;
    const int lane = tid & 31;

    const int b = blockIdx.z;
    const long aRow0 = (long)b * NN + blockIdx.y * 128;
    const long bRow0 = (long)b * DD + blockIdx.x * 128;
    const long outRow0 = aRow0;
    const int colBlk = blockIdx.x * 128;

    const __half* srcA   = A  + aRow0 * NN;
    const __half* srcB_h = Bh + bRow0 * NN;

    const int m0 = (wid & 3) * 32;
    const int n0 = (wid >> 2) * 64;

    const int ltile = lane >> 3;
    const int rowInTile = (lane & 7) + ((ltile & 1) << 3);
    const int kk = ltile >> 1;
    const int lx = lane & 7;

    float acc[2][8][4];
    #pragma unroll
    for (int a = 0; a < 2; a++)
        #pragma unroll
        for (int b2 = 0; b2 < 8; b2++)
            #pragma unroll
            for (int c = 0; c < 4; c++) acc[a][b2][c] = 0.0f;

    const int nk = NN / KT;   // 16

    auto issue = [&](int i) {
        const uint32_t stg = sb + (uint32_t)(i & 1) * STAGE1;
        const int k0 = i * KT;
        #pragma unroll
        for (int jj = 0; jj < 4; jj++) {           // A: 1024 chunks
            int cid = tid + jj * 256;
            int row = cid >> 3, c = cid & 7;
            cp_async16(stg + row * 128 + ((c ^ (row & 7)) << 4),
                       srcA + (size_t)row * NN + k0 + c * 8);
        }
        #pragma unroll
        for (int jj = 0; jj < 4; jj++) {           // B: 1024 chunks
            int cid = tid + jj * 256;
            int row = cid >> 3, c = cid & 7;
            cp_async16(stg + A1_TB + row * 128 + ((c ^ (row & 7)) << 4),
                       srcB_h + (size_t)row * NN + k0 + c * 8);
        }
        cp_commit();
    };

    issue(0);

    for (int i = 0; i < nk; i++) {
        if (i + 1 < nk) issue(i + 1);
        if (i + 1 < nk) cp_wait<1>(); else cp_wait<0>();
        __syncthreads();

        const uint32_t stg = sb + (uint32_t)(i & 1) * STAGE1;
        const uint32_t sA = stg, sBh = stg + A1_TB;

        #pragma unroll
        for (int ks = 0; ks < 4; ks++) {
            const uint32_t swz = (uint32_t)(((ks * 2 + kk) ^ lx) << 4);
            uint32_t af[2][4], bh[8][2];
            #pragma unroll
            for (int mf = 0; mf < 2; mf++) {
                uint32_t off = (uint32_t)((m0 + mf * 16 + rowInTile) * 128) + swz;
                ldsm4(af[mf], sA + off);
            }
            #pragma unroll
            for (int nh = 0; nh < 4; nh++) {
                uint32_t off = (uint32_t)((n0 + nh * 16 + rowInTile) * 128) + swz;
                uint32_t r[4];
                ldsm4(r, sBh + off);
                bh[nh * 2][0] = r[0]; bh[nh * 2][1] = r[2];
                bh[nh * 2 + 1][0] = r[1]; bh[nh * 2 + 1][1] = r[3];
            }
            #pragma unroll
            for (int mf = 0; mf < 2; mf++)
                #pragma unroll
                for (int nf = 0; nf < 8; nf++)
                    mma16816(acc[mf][nf], af[mf], bh[nf]);
        }
        __syncthreads();
    }

    // ---- epilogue: +X, write yh fp16 ----
    const int rr = lane >> 2;
    const int cc = (lane & 3) * 2;
    #pragma unroll
    for (int mf = 0; mf < 2; mf++) {
        #pragma unroll
        for (int hf = 0; hf < 2; hf++) {
            long grow = outRow0 + m0 + mf * 16 + rr + hf * 8;
            #pragma unroll
            for (int nf = 0; nf < 8; nf++) {
                int gcol = colBlk + n0 + nf * 8 + cc;
                size_t gi = (size_t)grow * DD + gcol;
                float v0 = acc[mf][nf][hf * 2 + 0];
                float v1 = acc[mf][nf][hf * 2 + 1];
                float2 xv = *reinterpret_cast<const float2*>(&Xadd[gi]);
                v0 += xv.x; v1 += xv.y;
                *reinterpret_cast<__half2*>(&OutH[gi]) =
                    __halves2half2(__float2half_rn(v0), __float2half_rn(v1));
            }
        }
    }
}

// ===== GEMM2 (64-wide, R14-proven): X' = relu((yh@Wh^T + 2b)/denom) ===========
#define A2_TB 16384                        // 128 rows x 128 B
#define B2_TB 8192                         // 64 rows x 128 B
#define STAGE2 (A2_TB + B2_TB)             // 24 KB
#define G2_SMEM (2 * STAGE2)               // 48 KB
#define TSTRIDE 136                        // transposed-stage row stride (halves)

__global__ void __launch_bounds__(256, 2)
gemm2_hmma(const __half* __restrict__ A, const __half* __restrict__ Bh,
           const float* __restrict__ bias, const float* __restrict__ denom,
           float* __restrict__ OutF, __half* __restrict__ OutT) {
    extern __shared__ char smem[];
    const uint32_t sb = smem_u32(smem);
    const int tid = threadIdx.x;
    const int wid = tid >> 5;
    const int lane = tid & 31;

    const long aRow0 = (long)blockIdx.y * 128;
    const long bRow0 = (long)blockIdx.x * 64;
    const int colBlk = blockIdx.x * 64;

    const __half* srcA   = A  + aRow0 * DD;
    const __half* srcB_h = Bh + bRow0 * DD;

    const int m0 = (wid & 3) * 32;
    const int n0 = (wid >> 2) * 32;

    const int ltile = lane >> 3;
    const int rowInTile = (lane & 7) + ((ltile & 1) << 3);
    const int kk = ltile >> 1;
    const int lx = lane & 7;

    float acc[2][4][4];
    #pragma unroll
    for (int a = 0; a < 2; a++)
        #pragma unroll
        for (int b2 = 0; b2 < 4; b2++)
            #pragma unroll
            for (int c = 0; c < 4; c++) acc[a][b2][c] = 0.0f;

    const int nk = DD / KT;   // 8

    auto issue = [&](int i) {
        const uint32_t stg = sb + (uint32_t)(i & 1) * STAGE2;
        const int k0 = i * KT;
        #pragma unroll
        for (int jj = 0; jj < 4; jj++) {           // A: 1024 chunks
            int cid = tid + jj * 256;
            int row = cid >> 3, c = cid & 7;
            cp_async16(stg + row * 128 + ((c ^ (row & 7)) << 4),
                       srcA + (size_t)row * DD + k0 + c * 8);
        }
        #pragma unroll
        for (int jj = 0; jj < 2; jj++) {           // B: 512 chunks
            int cid = tid + jj * 256;
            int row = cid >> 3, c = cid & 7;
            cp_async16(stg + A2_TB + row * 128 + ((c ^ (row & 7)) << 4),
                       srcB_h + (size_t)row * DD + k0 + c * 8);
        }
        cp_commit();
    };

    issue(0);

    for (int i = 0; i < nk; i++) {
        if (i + 1 < nk) issue(i + 1);
        if (i + 1 < nk) cp_wait<1>(); else cp_wait<0>();
        __syncthreads();

        const uint32_t stg = sb + (uint32_t)(i & 1) * STAGE2;
        const uint32_t sA = stg, sBh = stg + A2_TB;

        #pragma unroll
        for (int ks = 0; ks < 4; ks++) {
            const uint32_t swz = (uint32_t)(((ks * 2 + kk) ^ lx) << 4);
            uint32_t af[2][4], bh[4][2];
            #pragma unroll
            for (int mf = 0; mf < 2; mf++) {
                uint32_t off = (uint32_t)((m0 + mf * 16 + rowInTile) * 128) + swz;
                ldsm4(af[mf], sA + off);
            }
            #pragma unroll
            for (int nh = 0; nh < 2; nh++) {
                uint32_t off = (uint32_t)((n0 + nh * 16 + rowInTile) * 128) + swz;
                uint32_t r[4];
                ldsm4(r, sBh + off);
                bh[nh * 2][0] = r[0]; bh[nh * 2][1] = r[2];
                bh[nh * 2 + 1][0] = r[1]; bh[nh * 2 + 1][1] = r[3];
            }
            #pragma unroll
            for (int mf = 0; mf < 2; mf++)
                #pragma unroll
                for (int nf = 0; nf < 4; nf++)
                    mma16816(acc[mf][nf], af[mf], bh[nf]);
        }
        __syncthreads();
    }

    // ---- epilogue: relu((v + 2b)/denom) -> OutF; optionally stage x^T fp16 ----
    __half* sT = reinterpret_cast<__half*>(smem);   // 64 x 128 transposed stage
    const int rr = lane >> 2;
    const int cc = (lane & 3) * 2;
    #pragma unroll
    for (int mf = 0; mf < 2; mf++) {
        #pragma unroll
        for (int hf = 0; hf < 2; hf++) {
            long grow = aRow0 + m0 + mf * 16 + rr + hf * 8;
            float invd = 1.0f / denom[grow];
            int ml = m0 + mf * 16 + rr + hf * 8;   // local row 0..127
            #pragma unroll
            for (int nf = 0; nf < 4; nf++) {
                int dl = n0 + nf * 8 + cc;          // local col 0..63
                int gcol = colBlk + dl;
                size_t gi = (size_t)grow * DD + gcol;
                float2 bv = *reinterpret_cast<const float2*>(&bias[gcol]);
                float2 o;
                o.x = fmaxf((acc[mf][nf][hf * 2 + 0] + 2.0f * bv.x) * invd, 0.0f);
                o.y = fmaxf((acc[mf][nf][hf * 2 + 1] + 2.0f * bv.y) * invd, 0.0f);
                *reinterpret_cast<float2*>(&OutF[gi]) = o;
                if (OutT) {
                    sT[(dl + 0) * TSTRIDE + ml] = __float2half_rn(o.x);
                    sT[(dl + 1) * TSTRIDE + ml] = __float2half_rn(o.y);
                }
            }
        }
    }
    if (OutT) {
        __syncthreads();
        const int bb = (int)(aRow0 >> 10);          // aRow0 / NN
        const int m0g = (int)(aRow0 & (NN - 1));    // aRow0 % NN
        __half* dst = OutT + (size_t)bb * DD * NN + (size_t)colBlk * NN + m0g;
        for (int it = tid; it < 64 * 64; it += 256) {
            int d = it >> 6;
            int mw = (it & 63) * 2;
            uint32_t v = *reinterpret_cast<uint32_t*>(&sT[d * TSTRIDE + mw]);
            *reinterpret_cast<uint32_t*>(&dst[(size_t)d * NN + mw]) = v;
        }
    }
}

// ---------------- LayerNorm ----------------
__global__ void ln_kernel(const float* __restrict__ X, const float* __restrict__ g,
                          const float* __restrict__ b, float* __restrict__ out) {
    __shared__ float sh[32];
    const int row = blockIdx.x;
    const float* p = X + (size_t)row * DD;
    const int tid = threadIdx.x;
    float v0 = p[tid];
    float v1 = p[tid + 256];
    float mu = block_reduce_sum(v0 + v1, sh) * (1.0f / DD);
    float d0 = v0 - mu, d1 = v1 - mu;
    float var = block_reduce_sum(d0 * d0 + d1 * d1, sh) * (1.0f / DD);
    float r = rsqrtf(var + LN_EPS);
    out[(size_t)row * DD + tid] = d0 * r * g[tid] + b[tid];
    out[(size_t)row * DD + tid + 256] = d1 * r * g[tid + 256] + b[tid + 256];
}

__global__ void mask_kernel(const float* __restrict__ denom, const float* __restrict__ colsum,
                            float* __restrict__ out, int count) {
    int i = blockIdx.x * blockDim.x + threadIdx.x;
    if (i >= count) return;
    if (i < BB * NN) {
        float rs = denom[i] - 1.0f;
        out[i] = ((rs + colsum[i]) == 0.0f) ? 1.0f : 0.0f;
    } else {
        out[i] = 0.0f;
    }
}

// ---------------- launch ----------------
extern "C" void kernel_launch(void* const* d_in, const int* in_sizes, int n_in,
                              void* d_out, int out_size) {
    const float* adj = (const float*)d_in[0];
    const float* emb = (const float*)d_in[1];
    const float* W0w = (const float*)d_in[3];
    const float* W0b = (const float*)d_in[4];
    const float* W1w = (const float*)d_in[5];
    const float* W1b = (const float*)d_in[6];
    const float* lng = (const float*)d_in[7];
    const float* lnb = (const float*)d_in[8];
    float* out = (float*)d_out;

    float *denom, *colsum, *x;
    __half *adjh, *xth, *yh, *w0h, *w1h;
    cudaGetSymbolAddress((void**)&denom, g_denom);
    cudaGetSymbolAddress((void**)&colsum, g_colsum);
    cudaGetSymbolAddress((void**)&x, g_x);
    cudaGetSymbolAddress((void**)&adjh, g_adj_h);
    cudaGetSymbolAddress((void**)&xth, g_xT_h);
    cudaGetSymbolAddress((void**)&yh, g_y_h);
    cudaGetSymbolAddress((void**)&w0h, g_W0_h);
    cudaGetSymbolAddress((void**)&w1h, g_W1_h);

    cudaFuncSetAttribute(gemm1_hmma, cudaFuncAttributeMaxDynamicSharedMemorySize, G1_SMEM);
    cudaFuncSetAttribute(gemm2_hmma, cudaFuncAttributeMaxDynamicSharedMemorySize, G2_SMEM);

    dim3 tg(DD / 32, NN / 32, BB);
    dim3 tb(32, 8);
    dim3 ga(8, BB);
    dim3 g1(DD / 128, NN / 128, BB);        // (4, 8, 32)
    dim3 g2(DD / 64, (BB * NN) / 128, 1);   // (8, 256)
    int w4 = (DD * DD) / 4;

    zero_kernel<<<(BB * NN + 255) / 256, 256>>>(colsum, BB * NN);              // 1
    adj_pass_kernel<<<ga, 256>>>(adj, denom, colsum, adjh);                    // 2
    transpose_h<<<tg, tb>>>(emb, xth);                                         // 3
    splitW2_kernel<<<dim3((w4 + 255) / 256, 2), 256>>>(W0w, W1w, w0h, w1h);    // 4
    gemm1_hmma<<<g1, 256, G1_SMEM>>>(adjh, xth, emb, yh);                      // 5
    gemm2_hmma<<<g2, 256, G2_SMEM>>>(yh, w0h, W0b, denom, x, xth);             // 6 (writes x^T)
    gemm1_hmma<<<g1, 256, G1_SMEM>>>(adjh, xth, x, yh);                        // 7
    gemm2_hmma<<<g2, 256, G2_SMEM>>>(yh, w1h, W1b, denom, x, nullptr);         // 8
    ln_kernel<<<BB * NN, 256>>>(x, lng, lnb, out);                             // 9

    int extra = out_size - BB * NN * DD;
    if (extra > 0) {
        mask_kernel<<<(extra + 255) / 256, 256>>>(denom, colsum,
                                                  out + (size_t)BB * NN * DD, extra);
    }
}

// round 17
// speedup vs baseline: 1.2786x; 1.0215x over previous
#include <cuda_runtime.h>
#include <cuda_fp16.h>
#include <cstdint>

#define BB 32
#define NN 1024
#define DD 512
#define LN_EPS 1e-5f

// ---------------- scratch (no allocations allowed) ----------------
__device__ float  g_denom[BB * NN];
__device__ float  g_colsum[BB * NN];
__device__ float  g_x[BB * NN * DD];                 // fp32 layer activations
__device__ __half g_adj_h[(size_t)BB * NN * NN];     // adj fp16
__device__ __half g_xT_h[(size_t)BB * DD * NN];      // X^T fp16 (B of gemm1)
__device__ __half g_y_h[(size_t)BB * NN * DD];       // gemm1 output fp16 (A of gemm2)
__device__ __half g_W0_h[DD * DD];
__device__ __half g_W1_h[DD * DD];

// ---------------- PTX helpers (base sm_103-safe) ----------------
__device__ __forceinline__ uint32_t smem_u32(const void* p) {
    uint32_t a;
    asm("{ .reg .u64 t; cvta.to.shared.u64 t, %1; cvt.u32.u64 %0, t; }" : "=r"(a) : "l"(p));
    return a;
}
__device__ __forceinline__ void cp_async16(uint32_t dst, const void* src) {
    asm volatile("cp.async.cg.shared.global [%0], [%1], 16;" :: "r"(dst), "l"(src));
}
__device__ __forceinline__ void cp_commit() { asm volatile("cp.async.commit_group;" ::: "memory"); }
template <int N>
__device__ __forceinline__ void cp_wait() { asm volatile("cp.async.wait_group %0;" :: "n"(N) : "memory"); }

__device__ __forceinline__ void ldsm4(uint32_t* r, uint32_t addr) {
    asm volatile("ldmatrix.sync.aligned.m8n8.x4.shared.b16 {%0,%1,%2,%3}, [%4];"
                 : "=r"(r[0]), "=r"(r[1]), "=r"(r[2]), "=r"(r[3]) : "r"(addr));
}
__device__ __forceinline__ void mma16816(float* c, const uint32_t* a, const uint32_t* b) {
    asm volatile("mma.sync.aligned.m16n8k16.row.col.f32.f16.f16.f32 "
                 "{%0,%1,%2,%3}, {%4,%5,%6,%7}, {%8,%9}, {%0,%1,%2,%3};"
                 : "+f"(c[0]), "+f"(c[1]), "+f"(c[2]), "+f"(c[3])
                 : "r"(a[0]), "r"(a[1]), "r"(a[2]), "r"(a[3]), "r"(b[0]), "r"(b[1]));
}

// ---------------- reductions ----------------
__device__ __forceinline__ float block_reduce_sum(float v, float* sh) {
    __syncthreads();
    int tid = threadIdx.x;
    #pragma unroll
    for (int o = 16; o > 0; o >>= 1) v += __shfl_down_sync(0xffffffff, v, o);
    if ((tid & 31) == 0) sh[tid >> 5] = v;
    __syncthreads();
    if (tid < 32) {
        v = (tid < (int)(blockDim.x >> 5)) ? sh[tid] : 0.0f;
        #pragma unroll
        for (int o = 16; o > 0; o >>= 1) v += __shfl_down_sync(0xffffffff, v, o);
        if (tid == 0) sh[0] = v;
    }
    __syncthreads();
    return sh[0];
}

// ---------------- adj pass: rowsum+1 -> denom, colsum (atomic), fp16 ----------
__global__ void __launch_bounds__(256)
adj_pass_kernel(const float* __restrict__ adj, float* __restrict__ denom,
                float* __restrict__ colsum, __half* __restrict__ Ah) {
    __shared__ float rowacc[128];
    const int b = blockIdx.y;
    const int r0 = blockIdx.x * 128;
    const int tid = threadIdx.x;
    const int lane = tid & 31;
    const int col0 = tid * 4;

    for (int i = tid; i < 128; i += 256) rowacc[i] = 0.0f;
    __syncthreads();

    const float* src = adj + (size_t)b * NN * NN + (size_t)r0 * NN;
    __half* dh = Ah + (size_t)b * NN * NN + (size_t)r0 * NN;

    float cs0 = 0.f, cs1 = 0.f, cs2 = 0.f, cs3 = 0.f;

    for (int r = 0; r < 128; r++) {
        float4 v = *reinterpret_cast<const float4*>(&src[(size_t)r * NN + col0]);
        __half h0 = __float2half_rn(v.x), h1 = __float2half_rn(v.y);
        __half h2 = __float2half_rn(v.z), h3 = __float2half_rn(v.w);
        *reinterpret_cast<__half2*>(&dh[(size_t)r * NN + col0])     = __halves2half2(h0, h1);
        *reinterpret_cast<__half2*>(&dh[(size_t)r * NN + col0 + 2]) = __halves2half2(h2, h3);
        cs0 += v.x; cs1 += v.y; cs2 += v.z; cs3 += v.w;
        float s = (v.x + v.y) + (v.z + v.w);
        #pragma unroll
        for (int o = 16; o > 0; o >>= 1) s += __shfl_down_sync(0xffffffff, s, o);
        if (lane == 0) atomicAdd(&rowacc[r], s);
    }
    __syncthreads();
    if (tid < 128) denom[(size_t)b * NN + r0 + tid] = rowacc[tid] + 1.0f;
    float* cdst = colsum + (size_t)b * NN + col0;
    atomicAdd(cdst + 0, cs0);
    atomicAdd(cdst + 1, cs1);
    atomicAdd(cdst + 2, cs2);
    atomicAdd(cdst + 3, cs3);
}

__global__ void zero_kernel(float* __restrict__ p, int n) {
    int i = blockIdx.x * blockDim.x + threadIdx.x;
    if (i < n) p[i] = 0.0f;
}

// both weights fp32 -> fp16 (one launch)
__global__ void splitW2_kernel(const float* __restrict__ w0, const float* __restrict__ w1,
                               __half* __restrict__ h0, __half* __restrict__ h1) {
    int i = blockIdx.x * blockDim.x + threadIdx.x;
    if (i >= DD * DD / 4) return;
    const float* src = blockIdx.y ? w1 : w0;
    __half* dst = blockIdx.y ? h1 : h0;
    float4 v = reinterpret_cast<const float4*>(src)[i];
    reinterpret_cast<__half2*>(dst)[i * 2 + 0] =
        __halves2half2(__float2half_rn(v.x), __float2half_rn(v.y));
    reinterpret_cast<__half2*>(dst)[i * 2 + 1] =
        __halves2half2(__float2half_rn(v.z), __float2half_rn(v.w));
}

// x[b][m][d] fp32 -> x^T fp16 [b][d][m]
__global__ void transpose_h(const float* __restrict__ x, __half* __restrict__ th) {
    __shared__ float tile[32][33];
    int b = blockIdx.z;
    int m0 = blockIdx.y * 32, d0 = blockIdx.x * 32;
    const float* src = x + (size_t)b * NN * DD;
    int tx = threadIdx.x, ty = threadIdx.y;
    #pragma unroll
    for (int j = 0; j < 32; j += 8)
        tile[ty + j][tx] = src[(size_t)(m0 + ty + j) * DD + d0 + tx];
    __syncthreads();
    __half* dh = th + (size_t)b * DD * NN;
    #pragma unroll
    for (int j = 0; j < 32; j += 8)
        dh[(size_t)(d0 + ty + j) * NN + m0 + tx] = __float2half_rn(tile[tx][ty + j]);
}

// ================= GEMM1: Y = adj@x + x -> yh fp16 (128x128 CTA tile) =========
#define KT 64
#define A1_TB 16384                       // 128 rows x 128 B
#define B1_TB 16384                       // 128 rows x 128 B
#define STAGE1 (A1_TB + B1_TB)            // 32 KB
#define G1_SMEM (2 * STAGE1)              // 64 KB

__global__ void __launch_bounds__(256, 2)
gemm1_hmma(const __half* __restrict__ A, const __half* __restrict__ Bh,
           const float* __restrict__ Xadd, __half* __restrict__ OutH) {
    extern __shared__ char smem[];
    const uint32_t sb = smem_u32(smem);
    const int tid = threadIdx.x;
    const int wid = tid >> 5;
    const int lane = tid & 31;

    const int b = blockIdx.z;
    const long aRow0 = (long)b * NN + blockIdx.y * 128;
    const long bRow0 = (long)b * DD + blockIdx.x * 128;
    const long outRow0 = aRow0;
    const int colBlk = blockIdx.x * 128;

    const __half* srcA   = A  + aRow0 * NN;
    const __half* srcB_h = Bh + bRow0 * NN;

    const int m0 = (wid & 3) * 32;
    const int n0 = (wid >> 2) * 64;

    const int ltile = lane >> 3;
    const int rowInTile = (lane & 7) + ((ltile & 1) << 3);
    const int kk = ltile >> 1;
    const int lx = lane & 7;

    float acc[2][8][4];
    #pragma unroll
    for (int a = 0; a < 2; a++)
        #pragma unroll
        for (int b2 = 0; b2 < 8; b2++)
            #pragma unroll
            for (int c = 0; c < 4; c++) acc[a][b2][c] = 0.0f;

    const int nk = NN / KT;   // 16

    auto issue = [&](int i) {
        const uint32_t stg = sb + (uint32_t)(i & 1) * STAGE1;
        const int k0 = i * KT;
        #pragma unroll
        for (int jj = 0; jj < 4; jj++) {           // A: 1024 chunks
            int cid = tid + jj * 256;
            int row = cid >> 3, c = cid & 7;
            cp_async16(stg + row * 128 + ((c ^ (row & 7)) << 4),
                       srcA + (size_t)row * NN + k0 + c * 8);
        }
        #pragma unroll
        for (int jj = 0; jj < 4; jj++) {           // B: 1024 chunks
            int cid = tid + jj * 256;
            int row = cid >> 3, c = cid & 7;
            cp_async16(stg + A1_TB + row * 128 + ((c ^ (row & 7)) << 4),
                       srcB_h + (size_t)row * NN + k0 + c * 8);
        }
        cp_commit();
    };

    issue(0);

    for (int i = 0; i < nk; i++) {
        if (i + 1 < nk) issue(i + 1);
        if (i + 1 < nk) cp_wait<1>(); else cp_wait<0>();
        __syncthreads();

        const uint32_t stg = sb + (uint32_t)(i & 1) * STAGE1;
        const uint32_t sA = stg, sBh = stg + A1_TB;

        #pragma unroll
        for (int ks = 0; ks < 4; ks++) {
            const uint32_t swz = (uint32_t)(((ks * 2 + kk) ^ lx) << 4);
            uint32_t af[2][4], bh[8][2];
            #pragma unroll
            for (int mf = 0; mf < 2; mf++) {
                uint32_t off = (uint32_t)((m0 + mf * 16 + rowInTile) * 128) + swz;
                ldsm4(af[mf], sA + off);
            }
            #pragma unroll
            for (int nh = 0; nh < 4; nh++) {
                uint32_t off = (uint32_t)((n0 + nh * 16 + rowInTile) * 128) + swz;
                uint32_t r[4];
                ldsm4(r, sBh + off);
                bh[nh * 2][0] = r[0]; bh[nh * 2][1] = r[2];
                bh[nh * 2 + 1][0] = r[1]; bh[nh * 2 + 1][1] = r[3];
            }
            #pragma unroll
            for (int mf = 0; mf < 2; mf++)
                #pragma unroll
                for (int nf = 0; nf < 8; nf++)
                    mma16816(acc[mf][nf], af[mf], bh[nf]);
        }
        __syncthreads();
    }

    // ---- epilogue: +X, write yh fp16 ----
    const int rr = lane >> 2;
    const int cc = (lane & 3) * 2;
    #pragma unroll
    for (int mf = 0; mf < 2; mf++) {
        #pragma unroll
        for (int hf = 0; hf < 2; hf++) {
            long grow = outRow0 + m0 + mf * 16 + rr + hf * 8;
            #pragma unroll
            for (int nf = 0; nf < 8; nf++) {
                int gcol = colBlk + n0 + nf * 8 + cc;
                size_t gi = (size_t)grow * DD + gcol;
                float v0 = acc[mf][nf][hf * 2 + 0];
                float v1 = acc[mf][nf][hf * 2 + 1];
                float2 xv = *reinterpret_cast<const float2*>(&Xadd[gi]);
                v0 += xv.x; v1 += xv.y;
                *reinterpret_cast<__half2*>(&OutH[gi]) =
                    __halves2half2(__float2half_rn(v0), __float2half_rn(v1));
            }
        }
    }
}

// ===== GEMM2 (128-wide): X' = relu((yh@Wh^T + 2b)/denom) (+ optional x^T fp16) =
#define A2_TB 16384                        // 128 rows x 128 B
#define B2_TB 16384                        // 128 rows x 128 B
#define STAGE2 (A2_TB + B2_TB)             // 32 KB
#define G2_SMEM (2 * STAGE2)               // 64 KB
#define TSTRIDE 136                        // transposed-stage row stride (halves)

__global__ void __launch_bounds__(256, 2)
gemm2_hmma(const __half* __restrict__ A, const __half* __restrict__ Bh,
           const float* __restrict__ bias, const float* __restrict__ denom,
           float* __restrict__ OutF, __half* __restrict__ OutT) {
    extern __shared__ char smem[];
    const uint32_t sb = smem_u32(smem);
    const int tid = threadIdx.x;
    const int wid = tid >> 5;
    const int lane = tid & 31;

    const long aRow0 = (long)blockIdx.y * 128;
    const long bRow0 = (long)blockIdx.x * 128;
    const int colBlk = blockIdx.x * 128;

    const __half* srcA   = A  + aRow0 * DD;
    const __half* srcB_h = Bh + bRow0 * DD;

    const int m0 = (wid & 3) * 32;
    const int n0 = (wid >> 2) * 64;

    const int ltile = lane >> 3;
    const int rowInTile = (lane & 7) + ((ltile & 1) << 3);
    const int kk = ltile >> 1;
    const int lx = lane & 7;

    float acc[2][8][4];
    #pragma unroll
    for (int a = 0; a < 2; a++)
        #pragma unroll
        for (int b2 = 0; b2 < 8; b2++)
            #pragma unroll
            for (int c = 0; c < 4; c++) acc[a][b2][c] = 0.0f;

    const int nk = DD / KT;   // 8

    auto issue = [&](int i) {
        const uint32_t stg = sb + (uint32_t)(i & 1) * STAGE2;
        const int k0 = i * KT;
        #pragma unroll
        for (int jj = 0; jj < 4; jj++) {           // A: 1024 chunks
            int cid = tid + jj * 256;
            int row = cid >> 3, c = cid & 7;
            cp_async16(stg + row * 128 + ((c ^ (row & 7)) << 4),
                       srcA + (size_t)row * DD + k0 + c * 8);
        }
        #pragma unroll
        for (int jj = 0; jj < 4; jj++) {           // B: 1024 chunks
            int cid = tid + jj * 256;
            int row = cid >> 3, c = cid & 7;
            cp_async16(stg + A2_TB + row * 128 + ((c ^ (row & 7)) << 4),
                       srcB_h + (size_t)row * DD + k0 + c * 8);
        }
        cp_commit();
    };

    issue(0);

    for (int i = 0; i < nk; i++) {
        if (i + 1 < nk) issue(i + 1);
        if (i + 1 < nk) cp_wait<1>(); else cp_wait<0>();
        __syncthreads();

        const uint32_t stg = sb + (uint32_t)(i & 1) * STAGE2;
        const uint32_t sA = stg, sBh = stg + A2_TB;

        #pragma unroll
        for (int ks = 0; ks < 4; ks++) {
            const uint32_t swz = (uint32_t)(((ks * 2 + kk) ^ lx) << 4);
            uint32_t af[2][4], bh[8][2];
            #pragma unroll
            for (int mf = 0; mf < 2; mf++) {
                uint32_t off = (uint32_t)((m0 + mf * 16 + rowInTile) * 128) + swz;
                ldsm4(af[mf], sA + off);
            }
            #pragma unroll
            for (int nh = 0; nh < 4; nh++) {
                uint32_t off = (uint32_t)((n0 + nh * 16 + rowInTile) * 128) + swz;
                uint32_t r[4];
                ldsm4(r, sBh + off);
                bh[nh * 2][0] = r[0]; bh[nh * 2][1] = r[2];
                bh[nh * 2 + 1][0] = r[1]; bh[nh * 2 + 1][1] = r[3];
            }
            #pragma unroll
            for (int mf = 0; mf < 2; mf++)
                #pragma unroll
                for (int nf = 0; nf < 8; nf++)
                    mma16816(acc[mf][nf], af[mf], bh[nf]);
        }
        __syncthreads();
    }

    // ---- epilogue: relu((v + 2b)/denom) -> OutF; optionally stage x^T fp16 ----
    __half* sT = reinterpret_cast<__half*>(smem);   // 128 x 136 transposed stage
    const int rr = lane >> 2;
    const int cc = (lane & 3) * 2;
    #pragma unroll
    for (int mf = 0; mf < 2; mf++) {
        #pragma unroll
        for (int hf = 0; hf < 2; hf++) {
            long grow = aRow0 + m0 + mf * 16 + rr + hf * 8;
            float invd = 1.0f / denom[grow];
            int ml = m0 + mf * 16 + rr + hf * 8;   // local row 0..127
            #pragma unroll
            for (int nf = 0; nf < 8; nf++) {
                int dl = n0 + nf * 8 + cc;          // local col 0..127
                int gcol = colBlk + dl;
                size_t gi = (size_t)grow * DD + gcol;
                float2 bv = *reinterpret_cast<const float2*>(&bias[gcol]);
                float2 o;
                o.x = fmaxf((acc[mf][nf][hf * 2 + 0] + 2.0f * bv.x) * invd, 0.0f);
                o.y = fmaxf((acc[mf][nf][hf * 2 + 1] + 2.0f * bv.y) * invd, 0.0f);
                *reinterpret_cast<float2*>(&OutF[gi]) = o;
                if (OutT) {
                    sT[(dl + 0) * TSTRIDE + ml] = __float2half_rn(o.x);
                    sT[(dl + 1) * TSTRIDE + ml] = __float2half_rn(o.y);
                }
            }
        }
    }
    if (OutT) {
        __syncthreads();
        const int bb = (int)(aRow0 >> 10);          // aRow0 / NN
        const int m0g = (int)(aRow0 & (NN - 1));    // aRow0 % NN
        __half* dst = OutT + (size_t)bb * DD * NN + (size_t)colBlk * NN + m0g;
        for (int it = tid; it < 128 * 64; it += 256) {
            int d = it >> 6;
            int mw = (it & 63) * 2;
            uint32_t v = *reinterpret_cast<uint32_t*>(&sT[d * TSTRIDE + mw]);
            *reinterpret_cast<uint32_t*>(&dst[(size_t)d * NN + mw]) = v;
        }
    }
}

// ---------------- LayerNorm ----------------
__global__ void ln_kernel(const float* __restrict__ X, const float* __restrict__ g,
                          const float* __restrict__ b, float* __restrict__ out) {
    __shared__ float sh[32];
    const int row = blockIdx.x;
    const float* p = X + (size_t)row * DD;
    const int tid = threadIdx.x;
    float v0 = p[tid];
    float v1 = p[tid + 256];
    float mu = block_reduce_sum(v0 + v1, sh) * (1.0f / DD);
    float d0 = v0 - mu, d1 = v1 - mu;
    float var = block_reduce_sum(d0 * d0 + d1 * d1, sh) * (1.0f / DD);
    float r = rsqrtf(var + LN_EPS);
    out[(size_t)row * DD + tid] = d0 * r * g[tid] + b[tid];
    out[(size_t)row * DD + tid + 256] = d1 * r * g[tid + 256] + b[tid + 256];
}

__global__ void mask_kernel(const float* __restrict__ denom, const float* __restrict__ colsum,
                            float* __restrict__ out, int count) {
    int i = blockIdx.x * blockDim.x + threadIdx.x;
    if (i >= count) return;
    if (i < BB * NN) {
        float rs = denom[i] - 1.0f;
        out[i] = ((rs + colsum[i]) == 0.0f) ? 1.0f : 0.0f;
    } else {
        out[i] = 0.0f;
    }
}

// ---------------- launch ----------------
extern "C" void kernel_launch(void* const* d_in, const int* in_sizes, int n_in,
                              void* d_out, int out_size) {
    const float* adj = (const float*)d_in[0];
    const float* emb = (const float*)d_in[1];
    const float* W0w = (const float*)d_in[3];
    const float* W0b = (const float*)d_in[4];
    const float* W1w = (const float*)d_in[5];
    const float* W1b = (const float*)d_in[6];
    const float* lng = (const float*)d_in[7];
    const float* lnb = (const float*)d_in[8];
    float* out = (float*)d_out;

    float *denom, *colsum, *x;
    __half *adjh, *xth, *yh, *w0h, *w1h;
    cudaGetSymbolAddress((void**)&denom, g_denom);
    cudaGetSymbolAddress((void**)&colsum, g_colsum);
    cudaGetSymbolAddress((void**)&x, g_x);
    cudaGetSymbolAddress((void**)&adjh, g_adj_h);
    cudaGetSymbolAddress((void**)&xth, g_xT_h);
    cudaGetSymbolAddress((void**)&yh, g_y_h);
    cudaGetSymbolAddress((void**)&w0h, g_W0_h);
    cudaGetSymbolAddress((void**)&w1h, g_W1_h);

    cudaFuncSetAttribute(gemm1_hmma, cudaFuncAttributeMaxDynamicSharedMemorySize, G1_SMEM);
    cudaFuncSetAttribute(gemm2_hmma, cudaFuncAttributeMaxDynamicSharedMemorySize, G2_SMEM);

    dim3 tg(DD / 32, NN / 32, BB);
    dim3 tb(32, 8);
    dim3 ga(8, BB);
    dim3 g1(DD / 128, NN / 128, BB);        // (4, 8, 32)
    dim3 g2(DD / 128, (BB * NN) / 128, 1);  // (4, 256)
    int w4 = (DD * DD) / 4;

    zero_kernel<<<(BB * NN + 255) / 256, 256>>>(colsum, BB * NN);              // 1
    adj_pass_kernel<<<ga, 256>>>(adj, denom, colsum, adjh);                    // 2
    transpose_h<<<tg, tb>>>(emb, xth);                                         // 3
    splitW2_kernel<<<dim3((w4 + 255) / 256, 2), 256>>>(W0w, W1w, w0h, w1h);    // 4
    gemm1_hmma<<<g1, 256, G1_SMEM>>>(adjh, xth, emb, yh);                      // 5
    gemm2_hmma<<<g2, 256, G2_SMEM>>>(yh, w0h, W0b, denom, x, xth);             // 6 (writes x^T)
    gemm1_hmma<<<g1, 256, G1_SMEM>>>(adjh, xth, x, yh);                        // 7
    gemm2_hmma<<<g2, 256, G2_SMEM>>>(yh, w1h, W1b, denom, x, nullptr);         // 8
    ln_kernel<<<BB * NN, 256>>>(x, lng, lnb, out);                             // 9

    int extra = out_size - BB * NN * DD;
    if (extra > 0) {
        mask_kernel<<<(extra + 255) / 256, 256>>>(denom, colsum,
                                                  out + (size_t)BB * NN * DD, extra);
    }
}